// round 12
// baseline (speedup 1.0000x reference)
#include <cstdint>
#include <cuda_runtime.h>
#include <cuda_bf16.h>
#include <mma.h>
#include <math.h>

using namespace nvcuda;

// Problem constants (B=4, C=8, F=2048, H=512, Hf=1024, NH=8, dh=64)
#define NROWS_Q 8192
#define NROWS_K 65536
#define HD      512
#define HFF     1024

typedef __nv_bfloat16 bf16;

// ---------------- scratch (device globals; no allocation allowed) -----------
__device__ bf16 g_qsh[(size_t)NROWS_Q * HD];
__device__ bf16 g_qsl[(size_t)NROWS_Q * HD];
__device__ bf16 g_Qph[(size_t)NROWS_Q * HD];
__device__ bf16 g_Qpl[(size_t)NROWS_Q * HD];
__device__ float g_Qp[(size_t)NROWS_Q * HD];
__device__ float g_U  [(size_t)8 * NROWS_Q * HD];      // [head][row][512]
__device__ bf16 g_vbh[(size_t)NROWS_Q * 8 * HD];       // [row][head][512]
__device__ bf16 g_vbl[(size_t)NROWS_Q * 8 * HD];
__device__ bf16 g_Xh [(size_t)NROWS_Q * HD];
__device__ bf16 g_Xl [(size_t)NROWS_Q * HD];
__device__ bf16 g_H1h[(size_t)NROWS_Q * HD];
__device__ bf16 g_H1l[(size_t)NROWS_Q * HD];
__device__ bf16 g_FFh[(size_t)NROWS_Q * HFF];
__device__ bf16 g_FFl[(size_t)NROWS_Q * HFF];
__device__ bf16 g_Wqh[HD*HD],  g_Wql[HD*HD];
__device__ bf16 g_Wkth[HD*HD], g_Wktl[HD*HD];          // transposed Wk planes
__device__ bf16 g_Wvh[HD*HD],  g_Wvl[HD*HD];
__device__ bf16 g_Woh[HD*HD],  g_Wol[HD*HD];
__device__ bf16 g_W1h[HFF*HD], g_W1l[HFF*HD];
__device__ bf16 g_W2h[HD*HFF], g_W2l[HD*HFF];
__device__ float g_Xo[(size_t)NROWS_Q * HD];
__device__ float g_H1[(size_t)NROWS_Q * HD];
__device__ float g_Y [(size_t)NROWS_Q * HD];
__device__ float g_zero[HD];                           // zero bias (zero-init)

// ---------------- helpers ----------------------------------------------------
__device__ __forceinline__ void cp16(void* s, const void* g) {
    unsigned int sa = (unsigned int)__cvta_generic_to_shared(s);
    asm volatile("cp.async.cg.shared.global [%0], [%1], 16;\n" :: "r"(sa), "l"(g));
}
__device__ __forceinline__ void cp_commit() { asm volatile("cp.async.commit_group;\n"); }
template<int N> __device__ __forceinline__ void cp_wait() {
    asm volatile("cp.async.wait_group %0;\n" :: "n"(N));
}

// ---------------- split: fp32 -> bf16 hi/lo ---------------------------------
__global__ __launch_bounds__(256)
void split_kernel(const float* __restrict__ s, bf16* __restrict__ h,
                  bf16* __restrict__ l, int n)
{
    int i = (blockIdx.x * 256 + threadIdx.x) * 4;
    if (i >= n) return;
    float4 v = *reinterpret_cast<const float4*>(s + i);
    bf16 h0 = __float2bfloat16_rn(v.x);
    bf16 h1 = __float2bfloat16_rn(v.y);
    bf16 h2 = __float2bfloat16_rn(v.z);
    bf16 h3 = __float2bfloat16_rn(v.w);
    bf16 l0 = __float2bfloat16_rn(v.x - __bfloat162float(h0));
    bf16 l1 = __float2bfloat16_rn(v.y - __bfloat162float(h1));
    bf16 l2 = __float2bfloat16_rn(v.z - __bfloat162float(h2));
    bf16 l3 = __float2bfloat16_rn(v.w - __bfloat162float(h3));
    __nv_bfloat162 ph0; ph0.x = h0; ph0.y = h1;
    __nv_bfloat162 ph1; ph1.x = h2; ph1.y = h3;
    __nv_bfloat162 pl0; pl0.x = l0; pl0.y = l1;
    __nv_bfloat162 pl1; pl1.x = l2; pl1.y = l3;
    *reinterpret_cast<__nv_bfloat162*>(h + i)     = ph0;
    *reinterpret_cast<__nv_bfloat162*>(h + i + 2) = ph1;
    *reinterpret_cast<__nv_bfloat162*>(l + i)     = pl0;
    *reinterpret_cast<__nv_bfloat162*>(l + i + 2) = pl1;
}

// ---------------- transpose + split: T[p,q] = W[q,p] -> bf16 hi/lo ----------
__global__ __launch_bounds__(256)
void tsplit_kernel(const float* __restrict__ W, bf16* __restrict__ Th,
                   bf16* __restrict__ Tl, int dim)
{
    __shared__ float t[32][33];
    const int bx = blockIdx.x * 32, by = blockIdx.y * 32;
    const int tx = threadIdx.x & 31, ty = threadIdx.x >> 5;
    #pragma unroll
    for (int i = 0; i < 32; i += 8)
        t[ty + i][tx] = W[(size_t)(by + ty + i) * dim + bx + tx];
    __syncthreads();
    #pragma unroll
    for (int i = 0; i < 32; i += 8) {
        float v = t[tx][ty + i];
        bf16 h = __float2bfloat16_rn(v);
        size_t o = (size_t)(bx + ty + i) * dim + by + tx;
        Th[o] = h;
        Tl[o] = __float2bfloat16_rn(v - __bfloat162float(h));
    }
}

// ---------------- bf16-split GEMM (templated BN, strides + batch) -----------
// C[m,n] = sum_k A[m,k]*W[n,k] + bias[n], hi*hi + hi*lo + lo*hi.
// BM=128, BK=32, 256 threads.
//  BN=128: 2x4 warp grid, 64x32 warp tile (MFR=4)  — large-N GEMMs
//  BN= 64: 4x2 warp grid, 32x32 warp tile (MFR=2)  — per-head V-proj
template<int BN, bool RELU, bool RES, bool OUTF, bool SPLIT>
__global__ __launch_bounds__(256)
void gemm_bf16s(const bf16* __restrict__ Ah_, const bf16* __restrict__ Al_,
                int lda, size_t aB,
                const bf16* __restrict__ Wh_, const bf16* __restrict__ Wl_,
                int ldb, size_t wB,
                const float* __restrict__ bias_, size_t biasB,
                const float* __restrict__ res_,
                float* __restrict__ Cout_, bf16* __restrict__ Oh_,
                bf16* __restrict__ Ol_, int ldc, size_t cB, int K)
{
    constexpr int BM = 128, BK = 32;
    constexpr int LDA = 40;
    constexpr int ASZ = BM * LDA;
    constexpr int BSZ = BN * LDA;
    constexpr int STAGE_ELEMS = 2 * ASZ + 2 * BSZ;
    constexpr int LDC = BN + 4;
    constexpr int MFR = (BN == 128) ? 4 : 2;     // 16-row frags per warp (M)
    constexpr int WMN = (BN == 128) ? 2 : 4;     // warps along M
    constexpr int BITER = (BN * 4) / 256;        // B-chunk iters per plane

    extern __shared__ __align__(16) unsigned char smem_raw[];
    bf16* smem = reinterpret_cast<bf16*>(smem_raw);

    const int z = blockIdx.z;
    const bf16* Ah = Ah_ + (size_t)z * aB;
    const bf16* Al = Al_ + (size_t)z * aB;
    const bf16* Wh = Wh_ + (size_t)z * wB;
    const bf16* Wl = Wl_ + (size_t)z * wB;
    const float* bias = bias_ + (size_t)z * biasB;
    const float* res  = RES  ? res_  + (size_t)z * cB : nullptr;
    float* Cout = OUTF ? Cout_ + (size_t)z * cB : nullptr;
    bf16*  Oh   = SPLIT ? Oh_ + (size_t)z * cB : nullptr;
    bf16*  Ol   = SPLIT ? Ol_ + (size_t)z * cB : nullptr;

    const int tid  = threadIdx.x;
    const int warp = tid >> 5;
    const int wm   = warp % WMN;
    const int wn   = warp / WMN;
    const int bm0  = blockIdx.y * BM;
    const int bn0  = blockIdx.x * BN;
    const int NK   = K >> 5;

    wmma::fragment<wmma::accumulator, 16, 16, 16, float> acc[MFR][2];
    #pragma unroll
    for (int i = 0; i < MFR; i++)
        #pragma unroll
        for (int j = 0; j < 2; j++)
            wmma::fill_fragment(acc[i][j], 0.0f);

    auto load_stage = [&](int s, int k0) {
        bf16* dAh = smem + s * STAGE_ELEMS;
        bf16* dAl = dAh + ASZ;
        bf16* dBh = dAl + ASZ;
        bf16* dBl = dBh + BSZ;
        #pragma unroll
        for (int t = 0; t < 2; t++) {
            int chunk = tid + t * 256;
            int row = chunk >> 2;
            int c   = (chunk & 3) * 8;
            size_t goff = (size_t)(bm0 + row) * lda + k0 + c;
            cp16(dAh + row * LDA + c, Ah + goff);
            cp16(dAl + row * LDA + c, Al + goff);
        }
        #pragma unroll
        for (int t = 0; t < BITER; t++) {
            int chunk = tid + t * 256;
            int row = chunk >> 2;
            int c   = (chunk & 3) * 8;
            size_t goff = (size_t)(bn0 + row) * ldb + k0 + c;
            cp16(dBh + row * LDA + c, Wh + goff);
            cp16(dBl + row * LDA + c, Wl + goff);
        }
    };

    load_stage(0, 0);
    cp_commit();

    for (int kt = 0; kt < NK; kt++) {
        if (kt + 1 < NK) {
            load_stage((kt + 1) & 1, (kt + 1) * BK);
            cp_commit();
            cp_wait<1>();
        } else {
            cp_wait<0>();
        }
        __syncthreads();

        const bf16* sAh = smem + (kt & 1) * STAGE_ELEMS;
        const bf16* sAl = sAh + ASZ;
        const bf16* sBh = sAl + ASZ;
        const bf16* sBl = sBh + BSZ;

        #pragma unroll
        for (int kk = 0; kk < BK; kk += 16) {
            wmma::fragment<wmma::matrix_a, 16, 16, 16, bf16, wmma::row_major> ah[MFR], al[MFR];
            wmma::fragment<wmma::matrix_b, 16, 16, 16, bf16, wmma::col_major> bh[2], bl[2];
            #pragma unroll
            for (int i = 0; i < MFR; i++) {
                wmma::load_matrix_sync(ah[i], sAh + (wm * MFR * 16 + i * 16) * LDA + kk, LDA);
                wmma::load_matrix_sync(al[i], sAl + (wm * MFR * 16 + i * 16) * LDA + kk, LDA);
            }
            #pragma unroll
            for (int j = 0; j < 2; j++) {
                wmma::load_matrix_sync(bh[j], sBh + (wn * 32 + j * 16) * LDA + kk, LDA);
                wmma::load_matrix_sync(bl[j], sBl + (wn * 32 + j * 16) * LDA + kk, LDA);
            }
            #pragma unroll
            for (int i = 0; i < MFR; i++)
                #pragma unroll
                for (int j = 0; j < 2; j++) {
                    wmma::mma_sync(acc[i][j], ah[i], bh[j], acc[i][j]);
                    wmma::mma_sync(acc[i][j], ah[i], bl[j], acc[i][j]);
                    wmma::mma_sync(acc[i][j], al[i], bh[j], acc[i][j]);
                }
        }
        __syncthreads();
    }

    float* sC = reinterpret_cast<float*>(smem_raw);
    #pragma unroll
    for (int i = 0; i < MFR; i++)
        #pragma unroll
        for (int j = 0; j < 2; j++)
            wmma::store_matrix_sync(sC + (wm * MFR * 16 + i * 16) * LDC + wn * 32 + j * 16,
                                    acc[i][j], LDC, wmma::mem_row_major);
    __syncthreads();

    for (int idx = tid; idx < BM * BN; idx += 256) {
        int m = idx / BN;
        int n = idx % BN;
        size_t go = (size_t)(bm0 + m) * ldc + bn0 + n;
        float v = sC[m * LDC + n] + bias[bn0 + n];
        if (RES)  v += res[go];
        if (RELU) v  = fmaxf(v, 0.0f);
        if (OUTF) Cout[go] = v;
        if (SPLIT) {
            bf16 h = __float2bfloat16_rn(v);
            Oh[go] = h;
            Ol[go] = __float2bfloat16_rn(v - __bfloat162float(h));
        }
    }
}

// ---------------- fused attention on RAW k/v ---------------------------------
__global__ __launch_bounds__(256)
void attn2_kernel(const float* __restrict__ key, const float* __restrict__ value,
                  const float* __restrict__ bk)
{
    __shared__ float ks[8][HD];
    __shared__ float vs[8][HD];

    const int r   = blockIdx.x;
    const int tid = threadIdx.x;
    const int h   = tid >> 5;
    const int l   = tid & 31;

    const float4* kg = reinterpret_cast<const float4*>(key   + (size_t)r * 8 * HD);
    const float4* vg = reinterpret_cast<const float4*>(value + (size_t)r * 8 * HD);
    float4* ks4 = reinterpret_cast<float4*>(&ks[0][0]);
    float4* vs4 = reinterpret_cast<float4*>(&vs[0][0]);
    #pragma unroll
    for (int i = 0; i < 4; i++) {
        ks4[tid + i * 256] = kg[tid + i * 256];
        vs4[tid + i * 256] = vg[tid + i * 256];
    }
    __syncthreads();

    const float* qp = g_Qp + (size_t)r * HD + h * 64;
    const float* bh = bk + h * 64;
    float sb = qp[l * 2] * bh[l * 2] + qp[l * 2 + 1] * bh[l * 2 + 1];
    #pragma unroll
    for (int o = 16; o; o >>= 1) sb += __shfl_xor_sync(0xffffffffu, sb, o);

    const float* Urow = g_U + ((size_t)h * NROWS_Q + r) * HD;
    float4 Uv[4];
    #pragma unroll
    for (int t = 0; t < 4; t++)
        Uv[t] = *reinterpret_cast<const float4*>(Urow + l * 4 + t * 128);

    float s[8];
    #pragma unroll
    for (int c = 0; c < 8; c++) {
        float p = 0.0f;
        #pragma unroll
        for (int t = 0; t < 4; t++) {
            float4 kv = *reinterpret_cast<const float4*>(&ks[c][l * 4 + t * 128]);
            p += Uv[t].x * kv.x + Uv[t].y * kv.y + Uv[t].z * kv.z + Uv[t].w * kv.w;
        }
        #pragma unroll
        for (int o = 16; o; o >>= 1) p += __shfl_xor_sync(0xffffffffu, p, o);
        s[c] = (p + sb) * 0.125f;
    }

    float mx = s[0];
    #pragma unroll
    for (int c = 1; c < 8; c++) mx = fmaxf(mx, s[c]);
    float e[8], sum = 0.0f;
    #pragma unroll
    for (int c = 0; c < 8; c++) { e[c] = expf(s[c] - mx); sum += e[c]; }
    const float inv = 1.0f / sum;

    float4 a4[4];
    #pragma unroll
    for (int t = 0; t < 4; t++) { a4[t].x = a4[t].y = a4[t].z = a4[t].w = 0.0f; }
    #pragma unroll
    for (int c = 0; c < 8; c++) {
        const float a = e[c] * inv;
        #pragma unroll
        for (int t = 0; t < 4; t++) {
            float4 vv = *reinterpret_cast<const float4*>(&vs[c][l * 4 + t * 128]);
            a4[t].x += a * vv.x; a4[t].y += a * vv.y;
            a4[t].z += a * vv.z; a4[t].w += a * vv.w;
        }
    }

    const size_t base = ((size_t)r * 8 + h) * HD + l * 4;
    #pragma unroll
    for (int t = 0; t < 4; t++) {
        bf16 h0 = __float2bfloat16_rn(a4[t].x);
        bf16 h1 = __float2bfloat16_rn(a4[t].y);
        bf16 h2 = __float2bfloat16_rn(a4[t].z);
        bf16 h3 = __float2bfloat16_rn(a4[t].w);
        __nv_bfloat162 hp0; hp0.x = h0; hp0.y = h1;
        __nv_bfloat162 hp1; hp1.x = h2; hp1.y = h3;
        __nv_bfloat162 lp0;
        lp0.x = __float2bfloat16_rn(a4[t].x - __bfloat162float(h0));
        lp0.y = __float2bfloat16_rn(a4[t].y - __bfloat162float(h1));
        __nv_bfloat162 lp1;
        lp1.x = __float2bfloat16_rn(a4[t].z - __bfloat162float(h2));
        lp1.y = __float2bfloat16_rn(a4[t].w - __bfloat162float(h3));
        *reinterpret_cast<__nv_bfloat162*>(g_vbh + base + t * 128)     = hp0;
        *reinterpret_cast<__nv_bfloat162*>(g_vbh + base + t * 128 + 2) = hp1;
        *reinterpret_cast<__nv_bfloat162*>(g_vbl + base + t * 128)     = lp0;
        *reinterpret_cast<__nv_bfloat162*>(g_vbl + base + t * 128 + 2) = lp1;
    }
}

// ---------------- LayerNorm (optionally emits bf16 hi/lo too) ---------------
template<bool SPLIT>
__global__ __launch_bounds__(256)
void ln_kernel(const float* __restrict__ X, const float* __restrict__ gw,
               const float* __restrict__ bw, float* __restrict__ Out,
               bf16* __restrict__ Oh, bf16* __restrict__ Ol)
{
    const int r = blockIdx.x;
    const int t = threadIdx.x;
    const float* x = X + (size_t)r * HD;
    const float v0 = x[t];
    const float v1 = x[t + 256];

    __shared__ float red[8];
    __shared__ float s_mean, s_rstd;

    float s = v0 + v1;
    #pragma unroll
    for (int o = 16; o; o >>= 1) s += __shfl_xor_sync(0xffffffffu, s, o);
    if ((t & 31) == 0) red[t >> 5] = s;
    __syncthreads();
    if (t < 32) {
        float z = (t < 8) ? red[t] : 0.0f;
        #pragma unroll
        for (int o = 4; o; o >>= 1) z += __shfl_xor_sync(0xffffffffu, z, o);
        if (t == 0) s_mean = z * (1.0f / 512.0f);
    }
    __syncthreads();
    const float mean = s_mean;
    const float d0 = v0 - mean, d1 = v1 - mean;

    float qv = d0 * d0 + d1 * d1;
    #pragma unroll
    for (int o = 16; o; o >>= 1) qv += __shfl_xor_sync(0xffffffffu, qv, o);
    if ((t & 31) == 0) red[t >> 5] = qv;
    __syncthreads();
    if (t < 32) {
        float z = (t < 8) ? red[t] : 0.0f;
        #pragma unroll
        for (int o = 4; o; o >>= 1) z += __shfl_xor_sync(0xffffffffu, z, o);
        if (t == 0) s_rstd = rsqrtf(z * (1.0f / 512.0f) + 1e-5f);
    }
    __syncthreads();
    const float rs = s_rstd;
    float y0 = d0 * rs * gw[t]       + bw[t];
    float y1 = d1 * rs * gw[t + 256] + bw[t + 256];
    size_t o0 = (size_t)r * HD + t;
    Out[o0]       = y0;
    Out[o0 + 256] = y1;
    if (SPLIT) {
        bf16 h0 = __float2bfloat16_rn(y0);
        bf16 h1 = __float2bfloat16_rn(y1);
        Oh[o0]       = h0;
        Oh[o0 + 256] = h1;
        Ol[o0]       = __float2bfloat16_rn(y0 - __bfloat162float(h0));
        Ol[o0 + 256] = __float2bfloat16_rn(y1 - __bfloat162float(h1));
    }
}

// ---------------- launch ----------------------------------------------------
extern "C" void kernel_launch(void* const* d_in, const int* in_sizes, int n_in,
                              void* d_out, int out_size)
{
    (void)in_sizes; (void)n_in; (void)out_size;
    const float* query = (const float*)d_in[0];
    const float* key   = (const float*)d_in[1];
    const float* value = (const float*)d_in[2];
    const float* Wq    = (const float*)d_in[3];
    const float* bq    = (const float*)d_in[4];
    const float* Wk    = (const float*)d_in[5];
    const float* bk    = (const float*)d_in[6];
    const float* Wv    = (const float*)d_in[7];
    const float* bv    = (const float*)d_in[8];
    const float* Wo    = (const float*)d_in[9];
    const float* bo    = (const float*)d_in[10];
    const float* ln1_g = (const float*)d_in[11];
    const float* ln1_b = (const float*)d_in[12];
    const float* W1    = (const float*)d_in[13];
    const float* b1    = (const float*)d_in[14];
    const float* W2    = (const float*)d_in[15];
    const float* b2    = (const float*)d_in[16];
    const float* ln2_g = (const float*)d_in[17];
    const float* ln2_b = (const float*)d_in[18];
    float* out = (float*)d_out;

    bf16 *qsh,*qsl,*Qph,*Qpl,*vbh,*vbl,*Xh,*Xl,*H1h,*H1l,*FFh,*FFl;
    bf16 *Wqh,*Wql,*Wkth,*Wktl,*Wvh,*Wvl,*Woh,*Wol,*W1h,*W1l,*W2h,*W2l;
    float *Qp,*U,*Xo,*H1,*Y,*zero;
    cudaGetSymbolAddress((void**)&qsh, g_qsh);  cudaGetSymbolAddress((void**)&qsl, g_qsl);
    cudaGetSymbolAddress((void**)&Qph, g_Qph);  cudaGetSymbolAddress((void**)&Qpl, g_Qpl);
    cudaGetSymbolAddress((void**)&vbh, g_vbh);  cudaGetSymbolAddress((void**)&vbl, g_vbl);
    cudaGetSymbolAddress((void**)&Xh,  g_Xh );  cudaGetSymbolAddress((void**)&Xl,  g_Xl );
    cudaGetSymbolAddress((void**)&H1h, g_H1h);  cudaGetSymbolAddress((void**)&H1l, g_H1l);
    cudaGetSymbolAddress((void**)&FFh, g_FFh);  cudaGetSymbolAddress((void**)&FFl, g_FFl);
    cudaGetSymbolAddress((void**)&Wqh, g_Wqh);  cudaGetSymbolAddress((void**)&Wql, g_Wql);
    cudaGetSymbolAddress((void**)&Wkth,g_Wkth); cudaGetSymbolAddress((void**)&Wktl,g_Wktl);
    cudaGetSymbolAddress((void**)&Wvh, g_Wvh);  cudaGetSymbolAddress((void**)&Wvl, g_Wvl);
    cudaGetSymbolAddress((void**)&Woh, g_Woh);  cudaGetSymbolAddress((void**)&Wol, g_Wol);
    cudaGetSymbolAddress((void**)&W1h, g_W1h);  cudaGetSymbolAddress((void**)&W1l, g_W1l);
    cudaGetSymbolAddress((void**)&W2h, g_W2h);  cudaGetSymbolAddress((void**)&W2l, g_W2l);
    cudaGetSymbolAddress((void**)&Qp, g_Qp);    cudaGetSymbolAddress((void**)&U,  g_U);
    cudaGetSymbolAddress((void**)&Xo, g_Xo);    cudaGetSymbolAddress((void**)&H1, g_H1);
    cudaGetSymbolAddress((void**)&Y,  g_Y);     cudaGetSymbolAddress((void**)&zero, g_zero);

    // dynamic smem: BN=128 -> 81920 B, BN=64 -> 61440 B
    constexpr int SMEM128 = 2 * (2 * 128 * 40 + 2 * 128 * 40) * 2;
    constexpr int SMEM64  = 2 * (2 * 128 * 40 + 2 * 64  * 40) * 2;
    cudaFuncSetAttribute(gemm_bf16s<128,false,false,true,true>,
                         cudaFuncAttributeMaxDynamicSharedMemorySize, SMEM128);
    cudaFuncSetAttribute(gemm_bf16s<128,false,false,true,false>,
                         cudaFuncAttributeMaxDynamicSharedMemorySize, SMEM128);
    cudaFuncSetAttribute(gemm_bf16s<128,false,true,true,false>,
                         cudaFuncAttributeMaxDynamicSharedMemorySize, SMEM128);
    cudaFuncSetAttribute(gemm_bf16s<128,true,false,false,true>,
                         cudaFuncAttributeMaxDynamicSharedMemorySize, SMEM128);
    cudaFuncSetAttribute(gemm_bf16s<64,false,false,false,true>,
                         cudaFuncAttributeMaxDynamicSharedMemorySize, SMEM64);

    const dim3 blk(256);
    auto sgrid = [](int n) { return dim3((n / 4 + 255) / 256); };

    // launches 1-5: operand prep needed by Qp/U (ncu -s 5 lands on launch 6)
    split_kernel<<<sgrid(NROWS_Q*HD), blk>>>(query, qsh, qsl, NROWS_Q*HD);   // 1
    split_kernel<<<sgrid(HD*HD),  blk>>>(Wq, Wqh, Wql, HD*HD);               // 2
    tsplit_kernel<<<dim3(HD/32, HD/32), blk>>>(Wk, Wkth, Wktl, HD);          // 3
    split_kernel<<<sgrid(HD*HD),  blk>>>(Wv, Wvh, Wvl, HD*HD);               // 4
    split_kernel<<<sgrid(HD*HD),  blk>>>(Wo, Woh, Wol, HD*HD);               // 5

    // 6: Qp = query @ Wq^T + bq  (fp32 + bf16 split out)  <-- ncu target
    gemm_bf16s<128,false,false,true,true><<<dim3(HD/128, NROWS_Q/128, 1), blk, SMEM128>>>(
        qsh, qsl, HD, 0,  Wqh, Wql, HD, 0,  bq, 0,  nullptr,
        Qp, Qph, Qpl, HD, 0, HD);

    // 7: U_h = Qp_h @ Wkt_h  (8 batched GEMMs, K=64) -> U [head][row][512]
    gemm_bf16s<128,false,false,true,false><<<dim3(HD/128, NROWS_Q/128, 8), blk, SMEM128>>>(
        Qph, Qpl, HD, 64,  Wkth, Wktl, HD, 64,  zero, 0,  nullptr,
        U, nullptr, nullptr, HD, (size_t)NROWS_Q * HD, 64);

    // 8: fused attention on raw k/v -> vbar hi/lo
    attn2_kernel<<<NROWS_Q, blk>>>(key, value, bk);

    // 9: x_h = vbar_h @ Wv_h^T + bv_h  (8 batched GEMMs, N=64) -> X hi/lo
    gemm_bf16s<64,false,false,false,true><<<dim3(1, NROWS_Q/128, 8), blk, SMEM64>>>(
        vbh, vbl, 8*HD, HD,  Wvh, Wvl, HD, (size_t)64*HD,  bv, 64,  nullptr,
        nullptr, Xh, Xl, HD, 64, HD);

    // 10-11: output projection + residual(query), then LN1
    gemm_bf16s<128,false,true,true,false><<<dim3(HD/128, NROWS_Q/128, 1), blk, SMEM128>>>(
        Xh, Xl, HD, 0,  Woh, Wol, HD, 0,  bo, 0,  query,
        Xo, nullptr, nullptr, HD, 0, HD);
    ln_kernel<true><<<NROWS_Q, blk>>>(Xo, ln1_g, ln1_b, H1, H1h, H1l);

    // 12-13: FFN weight splits (needed just before FFN GEMMs)
    split_kernel<<<sgrid(HFF*HD), blk>>>(W1, W1h, W1l, HFF*HD);
    split_kernel<<<sgrid(HD*HFF), blk>>>(W2, W2h, W2l, HD*HFF);

    // 14-15: FFN1 (ReLU, bf16 hi/lo out), FFN2 (+residual H1)
    gemm_bf16s<128,true,false,false,true><<<dim3(HFF/128, NROWS_Q/128, 1), blk, SMEM128>>>(
        H1h, H1l, HD, 0,  W1h, W1l, HD, 0,  b1, 0,  nullptr,
        nullptr, FFh, FFl, HFF, 0, HD);
    gemm_bf16s<128,false,true,true,false><<<dim3(HD/128, NROWS_Q/128, 1), blk, SMEM128>>>(
        FFh, FFl, HFF, 0,  W2h, W2l, HFF, 0,  b2, 0,  H1,
        Y, nullptr, nullptr, HD, 0, HFF);

    // 16: LN2 -> output
    ln_kernel<false><<<NROWS_Q, blk>>>(Y, ln2_g, ln2_b, out, nullptr, nullptr);
}

// round 13
// speedup vs baseline: 1.0868x; 1.0868x over previous
#include <cstdint>
#include <cuda_runtime.h>
#include <cuda_bf16.h>
#include <mma.h>
#include <math.h>

using namespace nvcuda;

// Problem constants (B=4, C=8, F=2048, H=512, Hf=1024, NH=8, dh=64)
#define NROWS_Q 8192
#define NROWS_K 65536
#define HD      512
#define HFF     1024

typedef __nv_bfloat16 bf16;

// ---------------- scratch (device globals; no allocation allowed) -----------
__device__ bf16 g_qsh[(size_t)NROWS_Q * HD];
__device__ bf16 g_qsl[(size_t)NROWS_Q * HD];
__device__ bf16 g_Qph[(size_t)NROWS_Q * HD];
__device__ bf16 g_Qpl[(size_t)NROWS_Q * HD];
__device__ float g_U  [(size_t)8 * NROWS_Q * HD];      // [head][row][512]
__device__ bf16 g_vbh[(size_t)NROWS_Q * 8 * HD];       // [row][head][512]
__device__ bf16 g_vbl[(size_t)NROWS_Q * 8 * HD];
__device__ bf16 g_Xh [(size_t)NROWS_Q * HD];
__device__ bf16 g_Xl [(size_t)NROWS_Q * HD];
__device__ bf16 g_H1h[(size_t)NROWS_Q * HD];
__device__ bf16 g_H1l[(size_t)NROWS_Q * HD];
__device__ bf16 g_FFh[(size_t)NROWS_Q * HFF];
__device__ bf16 g_FFl[(size_t)NROWS_Q * HFF];
__device__ bf16 g_Wqh[HD*HD],  g_Wql[HD*HD];
__device__ bf16 g_Wkth[HD*HD], g_Wktl[HD*HD];          // transposed Wk planes
__device__ bf16 g_Wvh[HD*HD],  g_Wvl[HD*HD];
__device__ bf16 g_Woh[HD*HD],  g_Wol[HD*HD];
__device__ bf16 g_W1h[HFF*HD], g_W1l[HFF*HD];
__device__ bf16 g_W2h[HD*HFF], g_W2l[HD*HFF];
__device__ float g_Xo[(size_t)NROWS_Q * HD];
__device__ float g_H1[(size_t)NROWS_Q * HD];
__device__ float g_Y [(size_t)NROWS_Q * HD];
__device__ float g_zero[HD];                           // zero bias (zero-init)

// ---------------- helpers ----------------------------------------------------
__device__ __forceinline__ void cp16(void* s, const void* g) {
    unsigned int sa = (unsigned int)__cvta_generic_to_shared(s);
    asm volatile("cp.async.cg.shared.global [%0], [%1], 16;\n" :: "r"(sa), "l"(g));
}
__device__ __forceinline__ void cp_commit() { asm volatile("cp.async.commit_group;\n"); }
template<int N> __device__ __forceinline__ void cp_wait() {
    asm volatile("cp.async.wait_group %0;\n" :: "n"(N));
}

// ---------------- fused multi-tensor split: fp32 -> bf16 hi/lo --------------
// Compile-time block ranges: query 4096 | Wq 256 | Wv 256 | Wo 256 | W1 512 | W2 512
__global__ __launch_bounds__(256)
void msplit_kernel(const float* __restrict__ q,  bf16* __restrict__ qh,  bf16* __restrict__ ql,
                   const float* __restrict__ wq, bf16* __restrict__ wqh, bf16* __restrict__ wql,
                   const float* __restrict__ wv, bf16* __restrict__ wvh, bf16* __restrict__ wvl,
                   const float* __restrict__ wo, bf16* __restrict__ woh, bf16* __restrict__ wol,
                   const float* __restrict__ w1, bf16* __restrict__ w1h, bf16* __restrict__ w1l,
                   const float* __restrict__ w2, bf16* __restrict__ w2h, bf16* __restrict__ w2l)
{
    const int b = blockIdx.x;
    const float* s; bf16* h; bf16* l; int base;
    if      (b < 4096) { s = q;  h = qh;  l = ql;  base = 0;    }
    else if (b < 4352) { s = wq; h = wqh; l = wql; base = 4096; }
    else if (b < 4608) { s = wv; h = wvh; l = wvl; base = 4352; }
    else if (b < 4864) { s = wo; h = woh; l = wol; base = 4608; }
    else if (b < 5376) { s = w1; h = w1h; l = w1l; base = 4864; }
    else               { s = w2; h = w2h; l = w2l; base = 5376; }

    const int i = ((b - base) * 256 + threadIdx.x) * 4;
    float4 v = *reinterpret_cast<const float4*>(s + i);
    bf16 h0 = __float2bfloat16_rn(v.x);
    bf16 h1 = __float2bfloat16_rn(v.y);
    bf16 h2 = __float2bfloat16_rn(v.z);
    bf16 h3 = __float2bfloat16_rn(v.w);
    __nv_bfloat162 ph0; ph0.x = h0; ph0.y = h1;
    __nv_bfloat162 ph1; ph1.x = h2; ph1.y = h3;
    __nv_bfloat162 pl0;
    pl0.x = __float2bfloat16_rn(v.x - __bfloat162float(h0));
    pl0.y = __float2bfloat16_rn(v.y - __bfloat162float(h1));
    __nv_bfloat162 pl1;
    pl1.x = __float2bfloat16_rn(v.z - __bfloat162float(h2));
    pl1.y = __float2bfloat16_rn(v.w - __bfloat162float(h3));
    *reinterpret_cast<__nv_bfloat162*>(h + i)     = ph0;
    *reinterpret_cast<__nv_bfloat162*>(h + i + 2) = ph1;
    *reinterpret_cast<__nv_bfloat162*>(l + i)     = pl0;
    *reinterpret_cast<__nv_bfloat162*>(l + i + 2) = pl1;
}

// ---------------- transpose + split: T[p,q] = W[q,p] -> bf16 hi/lo ----------
__global__ __launch_bounds__(256)
void tsplit_kernel(const float* __restrict__ W, bf16* __restrict__ Th,
                   bf16* __restrict__ Tl, int dim)
{
    __shared__ float t[32][33];
    const int bx = blockIdx.x * 32, by = blockIdx.y * 32;
    const int tx = threadIdx.x & 31, ty = threadIdx.x >> 5;
    #pragma unroll
    for (int i = 0; i < 32; i += 8)
        t[ty + i][tx] = W[(size_t)(by + ty + i) * dim + bx + tx];
    __syncthreads();
    #pragma unroll
    for (int i = 0; i < 32; i += 8) {
        float v = t[tx][ty + i];
        bf16 h = __float2bfloat16_rn(v);
        size_t o = (size_t)(bx + ty + i) * dim + by + tx;
        Th[o] = h;
        Tl[o] = __float2bfloat16_rn(v - __bfloat162float(h));
    }
}

// ---------------- bf16-split GEMM: BN=64, BM=128, BK=32 ----------------------
// C[m,n] = sum_k A[m,k]*W[n,k] + bias[n], hi*hi + hi*lo + lo*hi.
// 256 threads, 8 warps (4Mx2N), 32x32 per warp. Double-buffered cp.async.
template<bool RELU, bool RES, bool OUTF, bool SPLIT>
__global__ __launch_bounds__(256)
void gemm_bf16s(const bf16* __restrict__ Ah_, const bf16* __restrict__ Al_,
                int lda, size_t aB,
                const bf16* __restrict__ Wh_, const bf16* __restrict__ Wl_,
                int ldb, size_t wB,
                const float* __restrict__ bias_, size_t biasB,
                const float* __restrict__ res_,
                float* __restrict__ Cout_, bf16* __restrict__ Oh_,
                bf16* __restrict__ Ol_, int ldc, size_t cB, int K)
{
    constexpr int BM = 128, BN = 64, BK = 32;
    constexpr int LDA = 40;
    constexpr int ASZ = BM * LDA;
    constexpr int BSZ = BN * LDA;
    constexpr int STAGE_ELEMS = 2 * ASZ + 2 * BSZ;
    constexpr int LDC = 68;

    extern __shared__ __align__(16) unsigned char smem_raw[];
    bf16* smem = reinterpret_cast<bf16*>(smem_raw);

    const int z = blockIdx.z;
    const bf16* Ah = Ah_ + (size_t)z * aB;
    const bf16* Al = Al_ + (size_t)z * aB;
    const bf16* Wh = Wh_ + (size_t)z * wB;
    const bf16* Wl = Wl_ + (size_t)z * wB;
    const float* bias = bias_ + (size_t)z * biasB;
    const float* res  = RES  ? res_  + (size_t)z * cB : nullptr;
    float* Cout = OUTF ? Cout_ + (size_t)z * cB : nullptr;
    bf16*  Oh   = SPLIT ? Oh_ + (size_t)z * cB : nullptr;
    bf16*  Ol   = SPLIT ? Ol_ + (size_t)z * cB : nullptr;

    const int tid  = threadIdx.x;
    const int warp = tid >> 5;
    const int wm   = warp & 3;
    const int wn   = warp >> 2;
    const int bm0  = blockIdx.y * BM;
    const int bn0  = blockIdx.x * BN;
    const int NK   = K >> 5;

    wmma::fragment<wmma::accumulator, 16, 16, 16, float> acc[2][2];
    #pragma unroll
    for (int i = 0; i < 2; i++)
        #pragma unroll
        for (int j = 0; j < 2; j++)
            wmma::fill_fragment(acc[i][j], 0.0f);

    auto load_stage = [&](int s, int k0) {
        bf16* dAh = smem + s * STAGE_ELEMS;
        bf16* dAl = dAh + ASZ;
        bf16* dBh = dAl + ASZ;
        bf16* dBl = dBh + BSZ;
        #pragma unroll
        for (int t = 0; t < 2; t++) {
            int chunk = tid + t * 256;
            int row = chunk >> 2;
            int c   = (chunk & 3) * 8;
            size_t goff = (size_t)(bm0 + row) * lda + k0 + c;
            cp16(dAh + row * LDA + c, Ah + goff);
            cp16(dAl + row * LDA + c, Al + goff);
        }
        {
            int row = tid >> 2;
            int c   = (tid & 3) * 8;
            size_t goff = (size_t)(bn0 + row) * ldb + k0 + c;
            cp16(dBh + row * LDA + c, Wh + goff);
            cp16(dBl + row * LDA + c, Wl + goff);
        }
    };

    load_stage(0, 0);
    cp_commit();

    for (int kt = 0; kt < NK; kt++) {
        if (kt + 1 < NK) {
            load_stage((kt + 1) & 1, (kt + 1) * BK);
            cp_commit();
            cp_wait<1>();
        } else {
            cp_wait<0>();
        }
        __syncthreads();

        const bf16* sAh = smem + (kt & 1) * STAGE_ELEMS;
        const bf16* sAl = sAh + ASZ;
        const bf16* sBh = sAl + ASZ;
        const bf16* sBl = sBh + BSZ;

        #pragma unroll
        for (int kk = 0; kk < BK; kk += 16) {
            wmma::fragment<wmma::matrix_a, 16, 16, 16, bf16, wmma::row_major> ah[2], al[2];
            wmma::fragment<wmma::matrix_b, 16, 16, 16, bf16, wmma::col_major> bh[2], bl[2];
            #pragma unroll
            for (int i = 0; i < 2; i++) {
                wmma::load_matrix_sync(ah[i], sAh + (wm * 32 + i * 16) * LDA + kk, LDA);
                wmma::load_matrix_sync(al[i], sAl + (wm * 32 + i * 16) * LDA + kk, LDA);
            }
            #pragma unroll
            for (int j = 0; j < 2; j++) {
                wmma::load_matrix_sync(bh[j], sBh + (wn * 32 + j * 16) * LDA + kk, LDA);
                wmma::load_matrix_sync(bl[j], sBl + (wn * 32 + j * 16) * LDA + kk, LDA);
            }
            #pragma unroll
            for (int i = 0; i < 2; i++)
                #pragma unroll
                for (int j = 0; j < 2; j++) {
                    wmma::mma_sync(acc[i][j], ah[i], bh[j], acc[i][j]);
                    wmma::mma_sync(acc[i][j], ah[i], bl[j], acc[i][j]);
                    wmma::mma_sync(acc[i][j], al[i], bh[j], acc[i][j]);
                }
        }
        __syncthreads();
    }

    float* sC = reinterpret_cast<float*>(smem_raw);
    #pragma unroll
    for (int i = 0; i < 2; i++)
        #pragma unroll
        for (int j = 0; j < 2; j++)
            wmma::store_matrix_sync(sC + (wm * 32 + i * 16) * LDC + wn * 32 + j * 16,
                                    acc[i][j], LDC, wmma::mem_row_major);
    __syncthreads();

    for (int idx = tid; idx < BM * BN; idx += 256) {
        int m = idx >> 6;
        int n = idx & 63;
        size_t go = (size_t)(bm0 + m) * ldc + bn0 + n;
        float v = sC[m * LDC + n] + bias[bn0 + n];
        if (RES)  v += res[go];
        if (RELU) v  = fmaxf(v, 0.0f);
        if (OUTF) Cout[go] = v;
        if (SPLIT) {
            bf16 h = __float2bfloat16_rn(v);
            Oh[go] = h;
            Ol[go] = __float2bfloat16_rn(v - __bfloat162float(h));
        }
    }
}

// ---------------- fused attention on RAW k/v ---------------------------------
// Block per query row r, warp per head h.
// s_c = U_h[r]·k_raw[r8+c] + Qp_h[r]·bk_h;  att = softmax(s/8);
// vbar_h[r] = sum_c att_c * v_raw[r8+c]  -> bf16 hi/lo.
// Qp reconstructed from bf16 hi+lo planes (error ~2^-18).
__global__ __launch_bounds__(256)
void attn2_kernel(const float* __restrict__ key, const float* __restrict__ value,
                  const float* __restrict__ bk)
{
    __shared__ float ks[8][HD];
    __shared__ float vs[8][HD];

    const int r   = blockIdx.x;
    const int tid = threadIdx.x;
    const int h   = tid >> 5;
    const int l   = tid & 31;

    const float4* kg = reinterpret_cast<const float4*>(key   + (size_t)r * 8 * HD);
    const float4* vg = reinterpret_cast<const float4*>(value + (size_t)r * 8 * HD);
    float4* ks4 = reinterpret_cast<float4*>(&ks[0][0]);
    float4* vs4 = reinterpret_cast<float4*>(&vs[0][0]);
    #pragma unroll
    for (int i = 0; i < 4; i++) {
        ks4[tid + i * 256] = kg[tid + i * 256];
        vs4[tid + i * 256] = vg[tid + i * 256];
    }
    __syncthreads();

    // score bias: Qp_h[r] . bk_h (Qp = hi + lo reconstruct)
    const size_t qo = (size_t)r * HD + h * 64 + l * 2;
    __nv_bfloat162 qh2 = *reinterpret_cast<const __nv_bfloat162*>(g_Qph + qo);
    __nv_bfloat162 ql2 = *reinterpret_cast<const __nv_bfloat162*>(g_Qpl + qo);
    const float* bh = bk + h * 64;
    float sb = (__bfloat162float(qh2.x) + __bfloat162float(ql2.x)) * bh[l * 2]
             + (__bfloat162float(qh2.y) + __bfloat162float(ql2.y)) * bh[l * 2 + 1];
    #pragma unroll
    for (int o = 16; o; o >>= 1) sb += __shfl_xor_sync(0xffffffffu, sb, o);

    const float* Urow = g_U + ((size_t)h * NROWS_Q + r) * HD;
    float4 Uv[4];
    #pragma unroll
    for (int t = 0; t < 4; t++)
        Uv[t] = *reinterpret_cast<const float4*>(Urow + l * 4 + t * 128);

    float s[8];
    #pragma unroll
    for (int c = 0; c < 8; c++) {
        float p = 0.0f;
        #pragma unroll
        for (int t = 0; t < 4; t++) {
            float4 kv = *reinterpret_cast<const float4*>(&ks[c][l * 4 + t * 128]);
            p += Uv[t].x * kv.x + Uv[t].y * kv.y + Uv[t].z * kv.z + Uv[t].w * kv.w;
        }
        #pragma unroll
        for (int o = 16; o; o >>= 1) p += __shfl_xor_sync(0xffffffffu, p, o);
        s[c] = (p + sb) * 0.125f;
    }

    float mx = s[0];
    #pragma unroll
    for (int c = 1; c < 8; c++) mx = fmaxf(mx, s[c]);
    float e[8], sum = 0.0f;
    #pragma unroll
    for (int c = 0; c < 8; c++) { e[c] = expf(s[c] - mx); sum += e[c]; }
    const float inv = 1.0f / sum;

    float4 a4[4];
    #pragma unroll
    for (int t = 0; t < 4; t++) { a4[t].x = a4[t].y = a4[t].z = a4[t].w = 0.0f; }
    #pragma unroll
    for (int c = 0; c < 8; c++) {
        const float a = e[c] * inv;
        #pragma unroll
        for (int t = 0; t < 4; t++) {
            float4 vv = *reinterpret_cast<const float4*>(&vs[c][l * 4 + t * 128]);
            a4[t].x += a * vv.x; a4[t].y += a * vv.y;
            a4[t].z += a * vv.z; a4[t].w += a * vv.w;
        }
    }

    const size_t base = ((size_t)r * 8 + h) * HD + l * 4;
    #pragma unroll
    for (int t = 0; t < 4; t++) {
        bf16 h0 = __float2bfloat16_rn(a4[t].x);
        bf16 h1 = __float2bfloat16_rn(a4[t].y);
        bf16 h2 = __float2bfloat16_rn(a4[t].z);
        bf16 h3 = __float2bfloat16_rn(a4[t].w);
        __nv_bfloat162 hp0; hp0.x = h0; hp0.y = h1;
        __nv_bfloat162 hp1; hp1.x = h2; hp1.y = h3;
        __nv_bfloat162 lp0;
        lp0.x = __float2bfloat16_rn(a4[t].x - __bfloat162float(h0));
        lp0.y = __float2bfloat16_rn(a4[t].y - __bfloat162float(h1));
        __nv_bfloat162 lp1;
        lp1.x = __float2bfloat16_rn(a4[t].z - __bfloat162float(h2));
        lp1.y = __float2bfloat16_rn(a4[t].w - __bfloat162float(h3));
        *reinterpret_cast<__nv_bfloat162*>(g_vbh + base + t * 128)     = hp0;
        *reinterpret_cast<__nv_bfloat162*>(g_vbh + base + t * 128 + 2) = hp1;
        *reinterpret_cast<__nv_bfloat162*>(g_vbl + base + t * 128)     = lp0;
        *reinterpret_cast<__nv_bfloat162*>(g_vbl + base + t * 128 + 2) = lp1;
    }
}

// ---------------- LayerNorm (optionally emits bf16 hi/lo too) ---------------
template<bool SPLIT>
__global__ __launch_bounds__(256)
void ln_kernel(const float* __restrict__ X, const float* __restrict__ gw,
               const float* __restrict__ bw, float* __restrict__ Out,
               bf16* __restrict__ Oh, bf16* __restrict__ Ol)
{
    const int r = blockIdx.x;
    const int t = threadIdx.x;
    const float* x = X + (size_t)r * HD;
    const float v0 = x[t];
    const float v1 = x[t + 256];

    __shared__ float red[8];
    __shared__ float s_mean, s_rstd;

    float s = v0 + v1;
    #pragma unroll
    for (int o = 16; o; o >>= 1) s += __shfl_xor_sync(0xffffffffu, s, o);
    if ((t & 31) == 0) red[t >> 5] = s;
    __syncthreads();
    if (t < 32) {
        float z = (t < 8) ? red[t] : 0.0f;
        #pragma unroll
        for (int o = 4; o; o >>= 1) z += __shfl_xor_sync(0xffffffffu, z, o);
        if (t == 0) s_mean = z * (1.0f / 512.0f);
    }
    __syncthreads();
    const float mean = s_mean;
    const float d0 = v0 - mean, d1 = v1 - mean;

    float qv = d0 * d0 + d1 * d1;
    #pragma unroll
    for (int o = 16; o; o >>= 1) qv += __shfl_xor_sync(0xffffffffu, qv, o);
    if ((t & 31) == 0) red[t >> 5] = qv;
    __syncthreads();
    if (t < 32) {
        float z = (t < 8) ? red[t] : 0.0f;
        #pragma unroll
        for (int o = 4; o; o >>= 1) z += __shfl_xor_sync(0xffffffffu, z, o);
        if (t == 0) s_rstd = rsqrtf(z * (1.0f / 512.0f) + 1e-5f);
    }
    __syncthreads();
    const float rs = s_rstd;
    float y0 = d0 * rs * gw[t]       + bw[t];
    float y1 = d1 * rs * gw[t + 256] + bw[t + 256];
    size_t o0 = (size_t)r * HD + t;
    Out[o0]       = y0;
    Out[o0 + 256] = y1;
    if (SPLIT) {
        bf16 h0 = __float2bfloat16_rn(y0);
        bf16 h1 = __float2bfloat16_rn(y1);
        Oh[o0]       = h0;
        Oh[o0 + 256] = h1;
        Ol[o0]       = __float2bfloat16_rn(y0 - __bfloat162float(h0));
        Ol[o0 + 256] = __float2bfloat16_rn(y1 - __bfloat162float(h1));
    }
}

// ---------------- launch ----------------------------------------------------
extern "C" void kernel_launch(void* const* d_in, const int* in_sizes, int n_in,
                              void* d_out, int out_size)
{
    (void)in_sizes; (void)n_in; (void)out_size;
    const float* query = (const float*)d_in[0];
    const float* key   = (const float*)d_in[1];
    const float* value = (const float*)d_in[2];
    const float* Wq    = (const float*)d_in[3];
    const float* bq    = (const float*)d_in[4];
    const float* Wk    = (const float*)d_in[5];
    const float* bk    = (const float*)d_in[6];
    const float* Wv    = (const float*)d_in[7];
    const float* bv    = (const float*)d_in[8];
    const float* Wo    = (const float*)d_in[9];
    const float* bo    = (const float*)d_in[10];
    const float* ln1_g = (const float*)d_in[11];
    const float* ln1_b = (const float*)d_in[12];
    const float* W1    = (const float*)d_in[13];
    const float* b1    = (const float*)d_in[14];
    const float* W2    = (const float*)d_in[15];
    const float* b2    = (const float*)d_in[16];
    const float* ln2_g = (const float*)d_in[17];
    const float* ln2_b = (const float*)d_in[18];
    float* out = (float*)d_out;

    bf16 *qsh,*qsl,*Qph,*Qpl,*vbh,*vbl,*Xh,*Xl,*H1h,*H1l,*FFh,*FFl;
    bf16 *Wqh,*Wql,*Wkth,*Wktl,*Wvh,*Wvl,*Woh,*Wol,*W1h,*W1l,*W2h,*W2l;
    float *U,*Xo,*H1,*Y,*zero;
    cudaGetSymbolAddress((void**)&qsh, g_qsh);  cudaGetSymbolAddress((void**)&qsl, g_qsl);
    cudaGetSymbolAddress((void**)&Qph, g_Qph);  cudaGetSymbolAddress((void**)&Qpl, g_Qpl);
    cudaGetSymbolAddress((void**)&vbh, g_vbh);  cudaGetSymbolAddress((void**)&vbl, g_vbl);
    cudaGetSymbolAddress((void**)&Xh,  g_Xh );  cudaGetSymbolAddress((void**)&Xl,  g_Xl );
    cudaGetSymbolAddress((void**)&H1h, g_H1h);  cudaGetSymbolAddress((void**)&H1l, g_H1l);
    cudaGetSymbolAddress((void**)&FFh, g_FFh);  cudaGetSymbolAddress((void**)&FFl, g_FFl);
    cudaGetSymbolAddress((void**)&Wqh, g_Wqh);  cudaGetSymbolAddress((void**)&Wql, g_Wql);
    cudaGetSymbolAddress((void**)&Wkth,g_Wkth); cudaGetSymbolAddress((void**)&Wktl,g_Wktl);
    cudaGetSymbolAddress((void**)&Wvh, g_Wvh);  cudaGetSymbolAddress((void**)&Wvl, g_Wvl);
    cudaGetSymbolAddress((void**)&Woh, g_Woh);  cudaGetSymbolAddress((void**)&Wol, g_Wol);
    cudaGetSymbolAddress((void**)&W1h, g_W1h);  cudaGetSymbolAddress((void**)&W1l, g_W1l);
    cudaGetSymbolAddress((void**)&W2h, g_W2h);  cudaGetSymbolAddress((void**)&W2l, g_W2l);
    cudaGetSymbolAddress((void**)&U,  g_U);
    cudaGetSymbolAddress((void**)&Xo, g_Xo);    cudaGetSymbolAddress((void**)&H1, g_H1);
    cudaGetSymbolAddress((void**)&Y,  g_Y);     cudaGetSymbolAddress((void**)&zero, g_zero);

    constexpr int SMEM = (2 * (2 * 128 * 40 + 2 * 64 * 40)) * 2;  // 61440 bytes
    cudaFuncSetAttribute(gemm_bf16s<false,false,false,true>,
                         cudaFuncAttributeMaxDynamicSharedMemorySize, SMEM);
    cudaFuncSetAttribute(gemm_bf16s<false,false,true,false>,
                         cudaFuncAttributeMaxDynamicSharedMemorySize, SMEM);
    cudaFuncSetAttribute(gemm_bf16s<false,true,true,false>,
                         cudaFuncAttributeMaxDynamicSharedMemorySize, SMEM);
    cudaFuncSetAttribute(gemm_bf16s<true,false,false,true>,
                         cudaFuncAttributeMaxDynamicSharedMemorySize, SMEM);

    const dim3 blk(256);

    // 1: fused splits (query + 5 weights), 2: Wk transpose-split
    msplit_kernel<<<5888, blk>>>(query, qsh, qsl,  Wq, Wqh, Wql,  Wv, Wvh, Wvl,
                                 Wo, Woh, Wol,  W1, W1h, W1l,  W2, W2h, W2l);
    tsplit_kernel<<<dim3(HD/32, HD/32), blk>>>(Wk, Wkth, Wktl, HD);

    // 3: Qp = query @ Wq^T + bq  (bf16 hi/lo only)
    gemm_bf16s<false,false,false,true><<<dim3(HD/64, NROWS_Q/128, 1), blk, SMEM>>>(
        qsh, qsl, HD, 0,  Wqh, Wql, HD, 0,  bq, 0,  nullptr,
        nullptr, Qph, Qpl, HD, 0, HD);

    // 4: U_h = Qp_h @ Wkt_h  (8 batched GEMMs, K=64) -> U [head][row][512]
    gemm_bf16s<false,false,true,false><<<dim3(HD/64, NROWS_Q/128, 8), blk, SMEM>>>(
        Qph, Qpl, HD, 64,  Wkth, Wktl, HD, 64,  zero, 0,  nullptr,
        U, nullptr, nullptr, HD, (size_t)NROWS_Q * HD, 64);

    // 5: fused attention on raw k/v -> vbar hi/lo
    attn2_kernel<<<NROWS_Q, blk>>>(key, value, bk);

    // 6: x_h = vbar_h @ Wv_h^T + bv_h  (8 batched GEMMs, N=64) -> X hi/lo
    gemm_bf16s<false,false,false,true><<<dim3(1, NROWS_Q/128, 8), blk, SMEM>>>(
        vbh, vbl, 8*HD, HD,  Wvh, Wvl, HD, (size_t)64*HD,  bv, 64,  nullptr,
        nullptr, Xh, Xl, HD, 64, HD);

    // 7-8: output projection + residual(query), then LN1
    gemm_bf16s<false,true,true,false><<<dim3(HD/64, NROWS_Q/128, 1), blk, SMEM>>>(
        Xh, Xl, HD, 0,  Woh, Wol, HD, 0,  bo, 0,  query,
        Xo, nullptr, nullptr, HD, 0, HD);
    ln_kernel<true><<<NROWS_Q, blk>>>(Xo, ln1_g, ln1_b, H1, H1h, H1l);

    // 9-10: FFN1 (ReLU, bf16 hi/lo out), FFN2 (+residual H1)
    gemm_bf16s<true,false,false,true><<<dim3(HFF/64, NROWS_Q/128, 1), blk, SMEM>>>(
        H1h, H1l, HD, 0,  W1h, W1l, HD, 0,  b1, 0,  nullptr,
        nullptr, FFh, FFl, HFF, 0, HD);
    gemm_bf16s<false,true,true,false><<<dim3(HD/64, NROWS_Q/128, 1), blk, SMEM>>>(
        FFh, FFl, HFF, 0,  W2h, W2l, HFF, 0,  b2, 0,  H1,
        Y, nullptr, nullptr, HD, 0, HFF);

    // 11: LN2 -> output
    ln_kernel<false><<<NROWS_Q, blk>>>(Y, ln2_g, ln2_b, out, nullptr, nullptr);
}

// round 17
// speedup vs baseline: 1.1342x; 1.0437x over previous
#include <cstdint>
#include <cuda_runtime.h>
#include <cuda_bf16.h>
#include <mma.h>
#include <math.h>

using namespace nvcuda;

// Problem constants (B=4, C=8, F=2048, H=512, Hf=1024, NH=8, dh=64)
#define NROWS_Q 8192
#define NROWS_K 65536
#define HD      512
#define HFF     1024

typedef __nv_bfloat16 bf16;

// ---------------- scratch (device globals; no allocation allowed) -----------
__device__ bf16 g_qsh[(size_t)NROWS_Q * HD];
__device__ bf16 g_qsl[(size_t)NROWS_Q * HD];
__device__ bf16 g_Qph[(size_t)NROWS_Q * HD];
__device__ bf16 g_Qpl[(size_t)NROWS_Q * HD];
__device__ float g_U  [(size_t)8 * NROWS_Q * HD];      // [head][row][512]
__device__ bf16 g_vbh[(size_t)NROWS_Q * 8 * HD];       // [row][head][512]
__device__ bf16 g_vbl[(size_t)NROWS_Q * 8 * HD];
__device__ bf16 g_Xh [(size_t)NROWS_Q * HD];
__device__ bf16 g_Xl [(size_t)NROWS_Q * HD];
__device__ bf16 g_H1h[(size_t)NROWS_Q * HD];
__device__ bf16 g_H1l[(size_t)NROWS_Q * HD];
__device__ bf16 g_FFh[(size_t)NROWS_Q * HFF];
__device__ bf16 g_FFl[(size_t)NROWS_Q * HFF];
__device__ bf16 g_Wqh[HD*HD],  g_Wql[HD*HD];
__device__ bf16 g_Wkth[HD*HD], g_Wktl[HD*HD];          // transposed Wk planes
__device__ bf16 g_Wvh[HD*HD],  g_Wvl[HD*HD];
__device__ bf16 g_Woh[HD*HD],  g_Wol[HD*HD];
__device__ bf16 g_W1h[HFF*HD], g_W1l[HFF*HD];
__device__ bf16 g_W2h[HD*HFF], g_W2l[HD*HFF];
__device__ float g_Xo[(size_t)NROWS_Q * HD];
__device__ float g_H1[(size_t)NROWS_Q * HD];
__device__ float g_Y [(size_t)NROWS_Q * HD];
__device__ float g_zero[HD];                           // zero bias (zero-init)

// ---------------- helpers ----------------------------------------------------
__device__ __forceinline__ void cp16(void* s, const void* g) {
    unsigned int sa = (unsigned int)__cvta_generic_to_shared(s);
    asm volatile("cp.async.cg.shared.global [%0], [%1], 16;\n" :: "r"(sa), "l"(g));
}
__device__ __forceinline__ void cp_commit() { asm volatile("cp.async.commit_group;\n"); }
template<int N> __device__ __forceinline__ void cp_wait() {
    asm volatile("cp.async.wait_group %0;\n" :: "n"(N));
}

// ---------------- fused multi-tensor split: fp32 -> bf16 hi/lo --------------
// Compile-time block ranges: query 4096 | Wq 256 | Wv 256 | Wo 256 | W1 512 | W2 512
__global__ __launch_bounds__(256)
void msplit_kernel(const float* __restrict__ q,  bf16* __restrict__ qh,  bf16* __restrict__ ql,
                   const float* __restrict__ wq, bf16* __restrict__ wqh, bf16* __restrict__ wql,
                   const float* __restrict__ wv, bf16* __restrict__ wvh, bf16* __restrict__ wvl,
                   const float* __restrict__ wo, bf16* __restrict__ woh, bf16* __restrict__ wol,
                   const float* __restrict__ w1, bf16* __restrict__ w1h, bf16* __restrict__ w1l,
                   const float* __restrict__ w2, bf16* __restrict__ w2h, bf16* __restrict__ w2l)
{
    const int b = blockIdx.x;
    const float* s; bf16* h; bf16* l; int base;
    if      (b < 4096) { s = q;  h = qh;  l = ql;  base = 0;    }
    else if (b < 4352) { s = wq; h = wqh; l = wql; base = 4096; }
    else if (b < 4608) { s = wv; h = wvh; l = wvl; base = 4352; }
    else if (b < 4864) { s = wo; h = woh; l = wol; base = 4608; }
    else if (b < 5376) { s = w1; h = w1h; l = w1l; base = 4864; }
    else               { s = w2; h = w2h; l = w2l; base = 5376; }

    const int i = ((b - base) * 256 + threadIdx.x) * 4;
    float4 v = *reinterpret_cast<const float4*>(s + i);
    bf16 h0 = __float2bfloat16_rn(v.x);
    bf16 h1 = __float2bfloat16_rn(v.y);
    bf16 h2 = __float2bfloat16_rn(v.z);
    bf16 h3 = __float2bfloat16_rn(v.w);
    __nv_bfloat162 ph0; ph0.x = h0; ph0.y = h1;
    __nv_bfloat162 ph1; ph1.x = h2; ph1.y = h3;
    __nv_bfloat162 pl0;
    pl0.x = __float2bfloat16_rn(v.x - __bfloat162float(h0));
    pl0.y = __float2bfloat16_rn(v.y - __bfloat162float(h1));
    __nv_bfloat162 pl1;
    pl1.x = __float2bfloat16_rn(v.z - __bfloat162float(h2));
    pl1.y = __float2bfloat16_rn(v.w - __bfloat162float(h3));
    *reinterpret_cast<__nv_bfloat162*>(h + i)     = ph0;
    *reinterpret_cast<__nv_bfloat162*>(h + i + 2) = ph1;
    *reinterpret_cast<__nv_bfloat162*>(l + i)     = pl0;
    *reinterpret_cast<__nv_bfloat162*>(l + i + 2) = pl1;
}

// ---------------- transpose + split: T[p,q] = W[q,p] -> bf16 hi/lo ----------
__global__ __launch_bounds__(256)
void tsplit_kernel(const float* __restrict__ W, bf16* __restrict__ Th,
                   bf16* __restrict__ Tl, int dim)
{
    __shared__ float t[32][33];
    const int bx = blockIdx.x * 32, by = blockIdx.y * 32;
    const int tx = threadIdx.x & 31, ty = threadIdx.x >> 5;
    #pragma unroll
    for (int i = 0; i < 32; i += 8)
        t[ty + i][tx] = W[(size_t)(by + ty + i) * dim + bx + tx];
    __syncthreads();
    #pragma unroll
    for (int i = 0; i < 32; i += 8) {
        float v = t[tx][ty + i];
        bf16 h = __float2bfloat16_rn(v);
        size_t o = (size_t)(bx + ty + i) * dim + by + tx;
        Th[o] = h;
        Tl[o] = __float2bfloat16_rn(v - __bfloat162float(h));
    }
}

// ---------------- bf16-split GEMM: BN=64, BM=128, BK=32 ----------------------
// C[m,n] = sum_k A[m,k]*W[n,k] + bias[n], hi*hi + hi*lo + lo*hi.
// 256 threads, 8 warps (4Mx2N), 32x32 per warp. Double-buffered cp.async.
// __launch_bounds__(256,3): cap regs ~85 so 3 CTAs/SM fit the register file
// (smem 61.4KB x 3 = 184KB < 227KB). R13 ncu: regs=100 -> 2 CTAs, occ 23.8%.
template<bool RELU, bool RES, bool OUTF, bool SPLIT>
__global__ __launch_bounds__(256, 3)
void gemm_bf16s(const bf16* __restrict__ Ah_, const bf16* __restrict__ Al_,
                int lda, size_t aB,
                const bf16* __restrict__ Wh_, const bf16* __restrict__ Wl_,
                int ldb, size_t wB,
                const float* __restrict__ bias_, size_t biasB,
                const float* __restrict__ res_,
                float* __restrict__ Cout_, bf16* __restrict__ Oh_,
                bf16* __restrict__ Ol_, int ldc, size_t cB, int K)
{
    constexpr int BM = 128, BN = 64, BK = 32;
    constexpr int LDA = 40;
    constexpr int ASZ = BM * LDA;
    constexpr int BSZ = BN * LDA;
    constexpr int STAGE_ELEMS = 2 * ASZ + 2 * BSZ;
    constexpr int LDC = 68;

    extern __shared__ __align__(16) unsigned char smem_raw[];
    bf16* smem = reinterpret_cast<bf16*>(smem_raw);

    const int z = blockIdx.z;
    const bf16* Ah = Ah_ + (size_t)z * aB;
    const bf16* Al = Al_ + (size_t)z * aB;
    const bf16* Wh = Wh_ + (size_t)z * wB;
    const bf16* Wl = Wl_ + (size_t)z * wB;
    const float* bias = bias_ + (size_t)z * biasB;
    const float* res  = RES  ? res_  + (size_t)z * cB : nullptr;
    float* Cout = OUTF ? Cout_ + (size_t)z * cB : nullptr;
    bf16*  Oh   = SPLIT ? Oh_ + (size_t)z * cB : nullptr;
    bf16*  Ol   = SPLIT ? Ol_ + (size_t)z * cB : nullptr;

    const int tid  = threadIdx.x;
    const int warp = tid >> 5;
    const int wm   = warp & 3;
    const int wn   = warp >> 2;
    const int bm0  = blockIdx.y * BM;
    const int bn0  = blockIdx.x * BN;
    const int NK   = K >> 5;

    wmma::fragment<wmma::accumulator, 16, 16, 16, float> acc[2][2];
    #pragma unroll
    for (int i = 0; i < 2; i++)
        #pragma unroll
        for (int j = 0; j < 2; j++)
            wmma::fill_fragment(acc[i][j], 0.0f);

    auto load_stage = [&](int s, int k0) {
        bf16* dAh = smem + s * STAGE_ELEMS;
        bf16* dAl = dAh + ASZ;
        bf16* dBh = dAl + ASZ;
        bf16* dBl = dBh + BSZ;
        #pragma unroll
        for (int t = 0; t < 2; t++) {
            int chunk = tid + t * 256;
            int row = chunk >> 2;
            int c   = (chunk & 3) * 8;
            size_t goff = (size_t)(bm0 + row) * lda + k0 + c;
            cp16(dAh + row * LDA + c, Ah + goff);
            cp16(dAl + row * LDA + c, Al + goff);
        }
        {
            int row = tid >> 2;
            int c   = (tid & 3) * 8;
            size_t goff = (size_t)(bn0 + row) * ldb + k0 + c;
            cp16(dBh + row * LDA + c, Wh + goff);
            cp16(dBl + row * LDA + c, Wl + goff);
        }
    };

    load_stage(0, 0);
    cp_commit();

    for (int kt = 0; kt < NK; kt++) {
        if (kt + 1 < NK) {
            load_stage((kt + 1) & 1, (kt + 1) * BK);
            cp_commit();
            cp_wait<1>();
        } else {
            cp_wait<0>();
        }
        __syncthreads();

        const bf16* sAh = smem + (kt & 1) * STAGE_ELEMS;
        const bf16* sAl = sAh + ASZ;
        const bf16* sBh = sAl + ASZ;
        const bf16* sBl = sBh + BSZ;

        #pragma unroll
        for (int kk = 0; kk < BK; kk += 16) {
            wmma::fragment<wmma::matrix_a, 16, 16, 16, bf16, wmma::row_major> ah[2], al[2];
            wmma::fragment<wmma::matrix_b, 16, 16, 16, bf16, wmma::col_major> bh[2], bl[2];
            #pragma unroll
            for (int i = 0; i < 2; i++) {
                wmma::load_matrix_sync(ah[i], sAh + (wm * 32 + i * 16) * LDA + kk, LDA);
                wmma::load_matrix_sync(al[i], sAl + (wm * 32 + i * 16) * LDA + kk, LDA);
            }
            #pragma unroll
            for (int j = 0; j < 2; j++) {
                wmma::load_matrix_sync(bh[j], sBh + (wn * 32 + j * 16) * LDA + kk, LDA);
                wmma::load_matrix_sync(bl[j], sBl + (wn * 32 + j * 16) * LDA + kk, LDA);
            }
            #pragma unroll
            for (int i = 0; i < 2; i++)
                #pragma unroll
                for (int j = 0; j < 2; j++) {
                    wmma::mma_sync(acc[i][j], ah[i], bh[j], acc[i][j]);
                    wmma::mma_sync(acc[i][j], ah[i], bl[j], acc[i][j]);
                    wmma::mma_sync(acc[i][j], al[i], bh[j], acc[i][j]);
                }
        }
        __syncthreads();
    }

    float* sC = reinterpret_cast<float*>(smem_raw);
    #pragma unroll
    for (int i = 0; i < 2; i++)
        #pragma unroll
        for (int j = 0; j < 2; j++)
            wmma::store_matrix_sync(sC + (wm * 32 + i * 16) * LDC + wn * 32 + j * 16,
                                    acc[i][j], LDC, wmma::mem_row_major);
    __syncthreads();

    for (int idx = tid; idx < BM * BN; idx += 256) {
        int m = idx >> 6;
        int n = idx & 63;
        size_t go = (size_t)(bm0 + m) * ldc + bn0 + n;
        float v = sC[m * LDC + n] + bias[bn0 + n];
        if (RES)  v += res[go];
        if (RELU) v  = fmaxf(v, 0.0f);
        if (OUTF) Cout[go] = v;
        if (SPLIT) {
            bf16 h = __float2bfloat16_rn(v);
            Oh[go] = h;
            Ol[go] = __float2bfloat16_rn(v - __bfloat162float(h));
        }
    }
}

// ---------------- fused attention on RAW k/v ---------------------------------
// Block per query row r, warp per head h.
// s_c = U_h[r]·k_raw[r8+c] + Qp_h[r]·bk_h;  att = softmax(s/8);
// vbar_h[r] = sum_c att_c * v_raw[r8+c]  -> bf16 hi/lo.
// Qp reconstructed from bf16 hi+lo planes (error ~2^-18).
__global__ __launch_bounds__(256)
void attn2_kernel(const float* __restrict__ key, const float* __restrict__ value,
                  const float* __restrict__ bk)
{
    __shared__ float ks[8][HD];
    __shared__ float vs[8][HD];

    const int r   = blockIdx.x;
    const int tid = threadIdx.x;
    const int h   = tid >> 5;
    const int l   = tid & 31;

    const float4* kg = reinterpret_cast<const float4*>(key   + (size_t)r * 8 * HD);
    const float4* vg = reinterpret_cast<const float4*>(value + (size_t)r * 8 * HD);
    float4* ks4 = reinterpret_cast<float4*>(&ks[0][0]);
    float4* vs4 = reinterpret_cast<float4*>(&vs[0][0]);
    #pragma unroll
    for (int i = 0; i < 4; i++) {
        ks4[tid + i * 256] = kg[tid + i * 256];
        vs4[tid + i * 256] = vg[tid + i * 256];
    }
    __syncthreads();

    // score bias: Qp_h[r] . bk_h (Qp = hi + lo reconstruct)
    const size_t qo = (size_t)r * HD + h * 64 + l * 2;
    __nv_bfloat162 qh2 = *reinterpret_cast<const __nv_bfloat162*>(g_Qph + qo);
    __nv_bfloat162 ql2 = *reinterpret_cast<const __nv_bfloat162*>(g_Qpl + qo);
    const float* bh = bk + h * 64;
    float sb = (__bfloat162float(qh2.x) + __bfloat162float(ql2.x)) * bh[l * 2]
             + (__bfloat162float(qh2.y) + __bfloat162float(ql2.y)) * bh[l * 2 + 1];
    #pragma unroll
    for (int o = 16; o; o >>= 1) sb += __shfl_xor_sync(0xffffffffu, sb, o);

    const float* Urow = g_U + ((size_t)h * NROWS_Q + r) * HD;
    float4 Uv[4];
    #pragma unroll
    for (int t = 0; t < 4; t++)
        Uv[t] = *reinterpret_cast<const float4*>(Urow + l * 4 + t * 128);

    float s[8];
    #pragma unroll
    for (int c = 0; c < 8; c++) {
        float p = 0.0f;
        #pragma unroll
        for (int t = 0; t < 4; t++) {
            float4 kv = *reinterpret_cast<const float4*>(&ks[c][l * 4 + t * 128]);
            p += Uv[t].x * kv.x + Uv[t].y * kv.y + Uv[t].z * kv.z + Uv[t].w * kv.w;
        }
        #pragma unroll
        for (int o = 16; o; o >>= 1) p += __shfl_xor_sync(0xffffffffu, p, o);
        s[c] = (p + sb) * 0.125f;
    }

    float mx = s[0];
    #pragma unroll
    for (int c = 1; c < 8; c++) mx = fmaxf(mx, s[c]);
    float e[8], sum = 0.0f;
    #pragma unroll
    for (int c = 0; c < 8; c++) { e[c] = expf(s[c] - mx); sum += e[c]; }
    const float inv = 1.0f / sum;

    float4 a4[4];
    #pragma unroll
    for (int t = 0; t < 4; t++) { a4[t].x = a4[t].y = a4[t].z = a4[t].w = 0.0f; }
    #pragma unroll
    for (int c = 0; c < 8; c++) {
        const float a = e[c] * inv;
        #pragma unroll
        for (int t = 0; t < 4; t++) {
            float4 vv = *reinterpret_cast<const float4*>(&vs[c][l * 4 + t * 128]);
            a4[t].x += a * vv.x; a4[t].y += a * vv.y;
            a4[t].z += a * vv.z; a4[t].w += a * vv.w;
        }
    }

    const size_t base = ((size_t)r * 8 + h) * HD + l * 4;
    #pragma unroll
    for (int t = 0; t < 4; t++) {
        bf16 h0 = __float2bfloat16_rn(a4[t].x);
        bf16 h1 = __float2bfloat16_rn(a4[t].y);
        bf16 h2 = __float2bfloat16_rn(a4[t].z);
        bf16 h3 = __float2bfloat16_rn(a4[t].w);
        __nv_bfloat162 hp0; hp0.x = h0; hp0.y = h1;
        __nv_bfloat162 hp1; hp1.x = h2; hp1.y = h3;
        __nv_bfloat162 lp0;
        lp0.x = __float2bfloat16_rn(a4[t].x - __bfloat162float(h0));
        lp0.y = __float2bfloat16_rn(a4[t].y - __bfloat162float(h1));
        __nv_bfloat162 lp1;
        lp1.x = __float2bfloat16_rn(a4[t].z - __bfloat162float(h2));
        lp1.y = __float2bfloat16_rn(a4[t].w - __bfloat162float(h3));
        *reinterpret_cast<__nv_bfloat162*>(g_vbh + base + t * 128)     = hp0;
        *reinterpret_cast<__nv_bfloat162*>(g_vbh + base + t * 128 + 2) = hp1;
        *reinterpret_cast<__nv_bfloat162*>(g_vbl + base + t * 128)     = lp0;
        *reinterpret_cast<__nv_bfloat162*>(g_vbl + base + t * 128 + 2) = lp1;
    }
}

// ---------------- LayerNorm (optionally emits bf16 hi/lo too) ---------------
template<bool SPLIT>
__global__ __launch_bounds__(256)
void ln_kernel(const float* __restrict__ X, const float* __restrict__ gw,
               const float* __restrict__ bw, float* __restrict__ Out,
               bf16* __restrict__ Oh, bf16* __restrict__ Ol)
{
    const int r = blockIdx.x;
    const int t = threadIdx.x;
    const float* x = X + (size_t)r * HD;
    const float v0 = x[t];
    const float v1 = x[t + 256];

    __shared__ float red[8];
    __shared__ float s_mean, s_rstd;

    float s = v0 + v1;
    #pragma unroll
    for (int o = 16; o; o >>= 1) s += __shfl_xor_sync(0xffffffffu, s, o);
    if ((t & 31) == 0) red[t >> 5] = s;
    __syncthreads();
    if (t < 32) {
        float z = (t < 8) ? red[t] : 0.0f;
        #pragma unroll
        for (int o = 4; o; o >>= 1) z += __shfl_xor_sync(0xffffffffu, z, o);
        if (t == 0) s_mean = z * (1.0f / 512.0f);
    }
    __syncthreads();
    const float mean = s_mean;
    const float d0 = v0 - mean, d1 = v1 - mean;

    float qv = d0 * d0 + d1 * d1;
    #pragma unroll
    for (int o = 16; o; o >>= 1) qv += __shfl_xor_sync(0xffffffffu, qv, o);
    if ((t & 31) == 0) red[t >> 5] = qv;
    __syncthreads();
    if (t < 32) {
        float z = (t < 8) ? red[t] : 0.0f;
        #pragma unroll
        for (int o = 4; o; o >>= 1) z += __shfl_xor_sync(0xffffffffu, z, o);
        if (t == 0) s_rstd = rsqrtf(z * (1.0f / 512.0f) + 1e-5f);
    }
    __syncthreads();
    const float rs = s_rstd;
    float y0 = d0 * rs * gw[t]       + bw[t];
    float y1 = d1 * rs * gw[t + 256] + bw[t + 256];
    size_t o0 = (size_t)r * HD + t;
    Out[o0]       = y0;
    Out[o0 + 256] = y1;
    if (SPLIT) {
        bf16 h0 = __float2bfloat16_rn(y0);
        bf16 h1 = __float2bfloat16_rn(y1);
        Oh[o0]       = h0;
        Oh[o0 + 256] = h1;
        Ol[o0]       = __float2bfloat16_rn(y0 - __bfloat162float(h0));
        Ol[o0 + 256] = __float2bfloat16_rn(y1 - __bfloat162float(h1));
    }
}

// ---------------- launch ----------------------------------------------------
extern "C" void kernel_launch(void* const* d_in, const int* in_sizes, int n_in,
                              void* d_out, int out_size)
{
    (void)in_sizes; (void)n_in; (void)out_size;
    const float* query = (const float*)d_in[0];
    const float* key   = (const float*)d_in[1];
    const float* value = (const float*)d_in[2];
    const float* Wq    = (const float*)d_in[3];
    const float* bq    = (const float*)d_in[4];
    const float* Wk    = (const float*)d_in[5];
    const float* bk    = (const float*)d_in[6];
    const float* Wv    = (const float*)d_in[7];
    const float* bv    = (const float*)d_in[8];
    const float* Wo    = (const float*)d_in[9];
    const float* bo    = (const float*)d_in[10];
    const float* ln1_g = (const float*)d_in[11];
    const float* ln1_b = (const float*)d_in[12];
    const float* W1    = (const float*)d_in[13];
    const float* b1    = (const float*)d_in[14];
    const float* W2    = (const float*)d_in[15];
    const float* b2    = (const float*)d_in[16];
    const float* ln2_g = (const float*)d_in[17];
    const float* ln2_b = (const float*)d_in[18];
    float* out = (float*)d_out;

    bf16 *qsh,*qsl,*Qph,*Qpl,*vbh,*vbl,*Xh,*Xl,*H1h,*H1l,*FFh,*FFl;
    bf16 *Wqh,*Wql,*Wkth,*Wktl,*Wvh,*Wvl,*Woh,*Wol,*W1h,*W1l,*W2h,*W2l;
    float *U,*Xo,*H1,*Y,*zero;
    cudaGetSymbolAddress((void**)&qsh, g_qsh);  cudaGetSymbolAddress((void**)&qsl, g_qsl);
    cudaGetSymbolAddress((void**)&Qph, g_Qph);  cudaGetSymbolAddress((void**)&Qpl, g_Qpl);
    cudaGetSymbolAddress((void**)&vbh, g_vbh);  cudaGetSymbolAddress((void**)&vbl, g_vbl);
    cudaGetSymbolAddress((void**)&Xh,  g_Xh );  cudaGetSymbolAddress((void**)&Xl,  g_Xl );
    cudaGetSymbolAddress((void**)&H1h, g_H1h);  cudaGetSymbolAddress((void**)&H1l, g_H1l);
    cudaGetSymbolAddress((void**)&FFh, g_FFh);  cudaGetSymbolAddress((void**)&FFl, g_FFl);
    cudaGetSymbolAddress((void**)&Wqh, g_Wqh);  cudaGetSymbolAddress((void**)&Wql, g_Wql);
    cudaGetSymbolAddress((void**)&Wkth,g_Wkth); cudaGetSymbolAddress((void**)&Wktl,g_Wktl);
    cudaGetSymbolAddress((void**)&Wvh, g_Wvh);  cudaGetSymbolAddress((void**)&Wvl, g_Wvl);
    cudaGetSymbolAddress((void**)&Woh, g_Woh);  cudaGetSymbolAddress((void**)&Wol, g_Wol);
    cudaGetSymbolAddress((void**)&W1h, g_W1h);  cudaGetSymbolAddress((void**)&W1l, g_W1l);
    cudaGetSymbolAddress((void**)&W2h, g_W2h);  cudaGetSymbolAddress((void**)&W2l, g_W2l);
    cudaGetSymbolAddress((void**)&U,  g_U);
    cudaGetSymbolAddress((void**)&Xo, g_Xo);    cudaGetSymbolAddress((void**)&H1, g_H1);
    cudaGetSymbolAddress((void**)&Y,  g_Y);     cudaGetSymbolAddress((void**)&zero, g_zero);

    constexpr int SMEM = (2 * (2 * 128 * 40 + 2 * 64 * 40)) * 2;  // 61440 bytes
    cudaFuncSetAttribute(gemm_bf16s<false,false,false,true>,
                         cudaFuncAttributeMaxDynamicSharedMemorySize, SMEM);
    cudaFuncSetAttribute(gemm_bf16s<false,false,true,false>,
                         cudaFuncAttributeMaxDynamicSharedMemorySize, SMEM);
    cudaFuncSetAttribute(gemm_bf16s<false,true,true,false>,
                         cudaFuncAttributeMaxDynamicSharedMemorySize, SMEM);
    cudaFuncSetAttribute(gemm_bf16s<true,false,false,true>,
                         cudaFuncAttributeMaxDynamicSharedMemorySize, SMEM);

    const dim3 blk(256);

    // 1: fused splits (query + 5 weights), 2: Wk transpose-split
    msplit_kernel<<<5888, blk>>>(query, qsh, qsl,  Wq, Wqh, Wql,  Wv, Wvh, Wvl,
                                 Wo, Woh, Wol,  W1, W1h, W1l,  W2, W2h, W2l);
    tsplit_kernel<<<dim3(HD/32, HD/32), blk>>>(Wk, Wkth, Wktl, HD);

    // 3: Qp = query @ Wq^T + bq  (bf16 hi/lo only)
    gemm_bf16s<false,false,false,true><<<dim3(HD/64, NROWS_Q/128, 1), blk, SMEM>>>(
        qsh, qsl, HD, 0,  Wqh, Wql, HD, 0,  bq, 0,  nullptr,
        nullptr, Qph, Qpl, HD, 0, HD);

    // 4: U_h = Qp_h @ Wkt_h  (8 batched GEMMs, K=64) -> U [head][row][512]
    gemm_bf16s<false,false,true,false><<<dim3(HD/64, NROWS_Q/128, 8), blk, SMEM>>>(
        Qph, Qpl, HD, 64,  Wkth, Wktl, HD, 64,  zero, 0,  nullptr,
        U, nullptr, nullptr, HD, (size_t)NROWS_Q * HD, 64);

    // 5: fused attention on raw k/v -> vbar hi/lo
    attn2_kernel<<<NROWS_Q, blk>>>(key, value, bk);

    // 6: x_h = vbar_h @ Wv_h^T + bv_h  (8 batched GEMMs, N=64) -> X hi/lo
    gemm_bf16s<false,false,false,true><<<dim3(1, NROWS_Q/128, 8), blk, SMEM>>>(
        vbh, vbl, 8*HD, HD,  Wvh, Wvl, HD, (size_t)64*HD,  bv, 64,  nullptr,
        nullptr, Xh, Xl, HD, 64, HD);

    // 7-8: output projection + residual(query), then LN1
    gemm_bf16s<false,true,true,false><<<dim3(HD/64, NROWS_Q/128, 1), blk, SMEM>>>(
        Xh, Xl, HD, 0,  Woh, Wol, HD, 0,  bo, 0,  query,
        Xo, nullptr, nullptr, HD, 0, HD);
    ln_kernel<true><<<NROWS_Q, blk>>>(Xo, ln1_g, ln1_b, H1, H1h, H1l);

    // 9-10: FFN1 (ReLU, bf16 hi/lo out), FFN2 (+residual H1)
    gemm_bf16s<true,false,false,true><<<dim3(HFF/64, NROWS_Q/128, 1), blk, SMEM>>>(
        H1h, H1l, HD, 0,  W1h, W1l, HD, 0,  b1, 0,  nullptr,
        nullptr, FFh, FFl, HFF, 0, HD);
    gemm_bf16s<false,true,true,false><<<dim3(HD/64, NROWS_Q/128, 1), blk, SMEM>>>(
        FFh, FFl, HFF, 0,  W2h, W2l, HFF, 0,  b2, 0,  H1,
        Y, nullptr, nullptr, HD, 0, HFF);

    // 11: LN2 -> output
    ln_kernel<false><<<NROWS_Q, blk>>>(Y, ln2_g, ln2_b, out, nullptr, nullptr);
}